// round 2
// baseline (speedup 1.0000x reference)
#include <cuda_runtime.h>
#include <math.h>

static const int T  = 2048;
static const int C  = 1024;
static const int NH = 16;
static const int HS = 64;
#define EPS_GN 0.00064f

// ---------------- scratch (one big __device__ global; no allocations) ----------------
__device__ float g_scratch[(size_t)17 * 2048 * 1024 + (size_t)2048 * 288];

// ---------------- K1: token shift + 6-way mix ----------------
__global__ void k_shift_mix(const float* __restrict__ x, const float* __restrict__ x_prev,
                            const int* __restrict__ cu, int ncu,
                            const float* __restrict__ mr, const float* __restrict__ mw,
                            const float* __restrict__ mk, const float* __restrict__ mv,
                            const float* __restrict__ ma, const float* __restrict__ mg,
                            float* __restrict__ oxr, float* __restrict__ oxw,
                            float* __restrict__ oxk, float* __restrict__ oxv,
                            float* __restrict__ oxa, float* __restrict__ oxg) {
    const int t = blockIdx.x;
    int kind = (t == 0) ? 1 : 0;   // 0: x[t-1], 1: zeros, 2: x_prev row
    int prow = 0;
    for (int i = 0; i + 1 < ncu; i++) if (cu[i] == t) { kind = 2; prow = i; }
    const int i4 = threadIdx.x;            // 0..255 covers C/4
    const int c = i4 * 4;
    const size_t off = (size_t)t * C + c;
    float4 xc = *(const float4*)(x + off);
    float4 pv;
    if (kind == 0)      pv = *(const float4*)(x + off - C);
    else if (kind == 2) pv = *(const float4*)(x_prev + (size_t)prow * C + c);
    else                pv = make_float4(0.f, 0.f, 0.f, 0.f);
    float4 dx = make_float4(pv.x - xc.x, pv.y - xc.y, pv.z - xc.z, pv.w - xc.w);
#define MIXOUT(dst, m) { \
    float4 mm = *(const float4*)((m) + c); \
    float4 r_ = make_float4(fmaf(dx.x, mm.x, xc.x), fmaf(dx.y, mm.y, xc.y), \
                            fmaf(dx.z, mm.z, xc.z), fmaf(dx.w, mm.w, xc.w)); \
    *(float4*)((dst) + off) = r_; }
    MIXOUT(oxr, mr) MIXOUT(oxw, mw) MIXOUT(oxk, mk)
    MIXOUT(oxv, mv) MIXOUT(oxa, ma) MIXOUT(oxg, mg)
#undef MIXOUT
}

// ---------------- K2/K8: fp32 NT GEMM  C[m][n] = sum_k A[m][k]*B[n][k] ----------------
__global__ void __launch_bounds__(256) k_gemm_nt(const float* __restrict__ A,
                                                 const float* __restrict__ B,
                                                 float* __restrict__ Cg) {
    __shared__ float As[8][128];
    __shared__ float Bs[8][128];
    const int bm = blockIdx.y * 128;
    const int bn = blockIdx.x * 128;
    const int tid = threadIdx.x;
    const int tx = tid & 15, ty = tid >> 4;
    const int lr = tid >> 1;
    const int lk = (tid & 1) * 4;
    float acc[8][8];
#pragma unroll
    for (int i = 0; i < 8; i++)
#pragma unroll
        for (int j = 0; j < 8; j++) acc[i][j] = 0.f;

    for (int k0 = 0; k0 < C; k0 += 8) {
        float4 av = *(const float4*)(A + (size_t)(bm + lr) * C + k0 + lk);
        float4 bv = *(const float4*)(B + (size_t)(bn + lr) * C + k0 + lk);
        __syncthreads();
        As[lk + 0][lr] = av.x; As[lk + 1][lr] = av.y; As[lk + 2][lr] = av.z; As[lk + 3][lr] = av.w;
        Bs[lk + 0][lr] = bv.x; Bs[lk + 1][lr] = bv.y; Bs[lk + 2][lr] = bv.z; Bs[lk + 3][lr] = bv.w;
        __syncthreads();
#pragma unroll
        for (int kk = 0; kk < 8; kk++) {
            float a[8], b[8];
            *(float4*)&a[0] = *(const float4*)&As[kk][ty * 8];
            *(float4*)&a[4] = *(const float4*)&As[kk][ty * 8 + 4];
            *(float4*)&b[0] = *(const float4*)&Bs[kk][tx * 8];
            *(float4*)&b[4] = *(const float4*)&Bs[kk][tx * 8 + 4];
#pragma unroll
            for (int i = 0; i < 8; i++)
#pragma unroll
                for (int j = 0; j < 8; j++)
                    acc[i][j] = fmaf(a[i], b[j], acc[i][j]);
        }
    }
#pragma unroll
    for (int i = 0; i < 8; i++) {
        float* row = Cg + (size_t)(bm + ty * 8 + i) * C + bn + tx * 8;
        *(float4*)row       = make_float4(acc[i][0], acc[i][1], acc[i][2], acc[i][3]);
        *(float4*)(row + 4) = make_float4(acc[i][4], acc[i][5], acc[i][6], acc[i][7]);
    }
}

// ---------------- K3: stage-1 LoRA GEMM  out[t][j] = act( X[t,:] @ W[:,j] ) ----------------
template <int KO, int ACT>
__global__ void __launch_bounds__(256) k_stage1(const float* __restrict__ X,
                                                const float* __restrict__ W,
                                                float* __restrict__ out) {
    __shared__ float Xs[32][33];
    __shared__ float Ws[32][KO];
    const int t0 = blockIdx.x * 32;
    const int tid = threadIdx.x;
    const int j = tid % KO;
    const int tg = tid / KO;
    const int RPT = 256 / KO;
    const int NT = 32 / RPT;
    float acc[NT];
#pragma unroll
    for (int tt = 0; tt < NT; tt++) acc[tt] = 0.f;

    for (int cb = 0; cb < C; cb += 32) {
#pragma unroll
        for (int i = tid; i < 32 * 32; i += 256)
            Xs[i >> 5][i & 31] = X[(size_t)(t0 + (i >> 5)) * C + cb + (i & 31)];
#pragma unroll
        for (int i = tid; i < 32 * KO; i += 256)
            Ws[i / KO][i % KO] = W[(size_t)(cb + i / KO) * KO + (i % KO)];
        __syncthreads();
#pragma unroll
        for (int cc = 0; cc < 32; cc++) {
            float wv = Ws[cc][j];
#pragma unroll
            for (int tt = 0; tt < NT; tt++)
                acc[tt] = fmaf(Xs[tg * NT + tt][cc], wv, acc[tt]);
        }
        __syncthreads();
    }
#pragma unroll
    for (int tt = 0; tt < NT; tt++) {
        float val = acc[tt];
        if (ACT == 1) val = tanhf(val);
        else if (ACT == 2) val = 1.f / (1.f + expf(-val));
        out[(size_t)(t0 + tg * NT + tt) * KO + j] = val;
    }
}

// ---------------- K4: stage-2 LoRA GEMM + fused epilogue ----------------
template <int KI, int EPI>
__global__ void __launch_bounds__(128) k_stage2(const float* __restrict__ Hh,
                                                const float* __restrict__ W2,
                                                const float* __restrict__ bias,
                                                const float* __restrict__ e1,
                                                const float* __restrict__ e2,
                                                float* __restrict__ out) {
    __shared__ float Hs[16][KI];
    const int tb = blockIdx.y * 16;
    const int o = blockIdx.x * 128 + threadIdx.x;
    for (int i = threadIdx.x; i < 16 * KI; i += 128)
        Hs[i / KI][i % KI] = Hh[(size_t)(tb + i / KI) * KI + (i % KI)];
    __syncthreads();
    float acc[16];
#pragma unroll
    for (int t = 0; t < 16; t++) acc[t] = 0.f;
#pragma unroll 8
    for (int cdx = 0; cdx < KI; cdx++) {
        float wv = W2[(size_t)cdx * C + o];
#pragma unroll
        for (int t = 0; t < 16; t++)
            acc[t] = fmaf(Hs[t][cdx], wv, acc[t]);
    }
    float bv = (EPI == 3) ? 0.f : bias[o];
#pragma unroll
    for (int t = 0; t < 16; t++) {
        size_t idx = (size_t)(tb + t) * C + o;
        float zv = acc[t] + bv;
        float res;
        if (EPI == 0) {
            float xn = -zv;
            float sp = (xn > 20.f) ? xn : log1pf(expf(xn));
            res = expf(-expf(-sp - 0.5f));
        } else if (EPI == 1) {
            res = 1.f / (1.f + expf(-zv));
        } else if (EPI == 2) {
            float sg = 1.f / (1.f + expf(-zv));
            float vr = e1[idx];
            res = fmaf(e2[idx] - vr, sg, vr);
        } else {
            res = zv;
        }
        out[idx] = res;
    }
}

// ---------------- K5: scan-input prep (kk normalize, aa, bb, k_adj) ----------------
__global__ void k_prep(const float* __restrict__ kin, const float* __restrict__ ain,
                       const float* __restrict__ kkw, const float* __restrict__ kaw,
                       float* __restrict__ aab, float* __restrict__ bbb,
                       float* __restrict__ kadj) {
    const int t = blockIdx.x;
    const int tid = threadIdx.x;
    const int cbase = tid * 4;
    const size_t idx = (size_t)t * C + cbase;
    float4 kv = *(const float4*)(kin + idx);
    float4 av = *(const float4*)(ain + idx);
    float4 kw = *(const float4*)(kkw + cbase);
    float4 aw = *(const float4*)(kaw + cbase);
    float4 kk = make_float4(kv.x * kw.x, kv.y * kw.y, kv.z * kw.z, kv.w * kw.w);
    float ss = kk.x * kk.x + kk.y * kk.y + kk.z * kk.z + kk.w * kk.w;
#pragma unroll
    for (int off = 8; off > 0; off >>= 1)
        ss += __shfl_xor_sync(0xffffffffu, ss, off);
    float inv = 1.f / fmaxf(sqrtf(ss), 1e-12f);
    float4 kn = make_float4(kk.x * inv, kk.y * inv, kk.z * inv, kk.w * inv);
    *(float4*)(aab + idx) = make_float4(-kn.x, -kn.y, -kn.z, -kn.w);
    *(float4*)(bbb + idx) = make_float4(kn.x * av.x, kn.y * av.y, kn.z * av.z, kn.w * av.w);
    *(float4*)(kadj + idx) = make_float4(
        kv.x * fmaf(av.x - 1.f, aw.x, 1.f),
        kv.y * fmaf(av.y - 1.f, aw.y, 1.f),
        kv.z * fmaf(av.z - 1.f, aw.z, 1.f),
        kv.w * fmaf(av.w - 1.f, aw.w, 1.f));
}

// ---------------- K6: RWKV-7 serial scan ----------------
__global__ void __launch_bounds__(32) k_scan(const float* __restrict__ rb,
                                             const float* __restrict__ ewb,
                                             const float* __restrict__ aab,
                                             const float* __restrict__ bbb,
                                             const float* __restrict__ kb,
                                             const float* __restrict__ vb,
                                             const float* __restrict__ S0,
                                             float* __restrict__ y) {
    __shared__ float sh[2][6][HS];
    const int h  = blockIdx.x;
    const int vg = blockIdx.y;
    const int tid = threadIdx.x;
    const int jg = tid & 3;
    const int vr = tid >> 2;
    const int vrow = vg * 8 + vr;
    const int jb = jg * 16;
    float S[16];
#pragma unroll
    for (int i = 0; i < 16; i++)
        S[i] = S0[(size_t)h * HS * HS + (size_t)vrow * HS + jb + i];

    const int lo = tid * 2;
    const size_t hbase = (size_t)h * HS + lo;
    float2 pr, pe, pa, pb, pk, pv;
#define LDSTEP(tt) { const size_t off = (size_t)(tt) * C + hbase; \
    pr = *(const float2*)(rb  + off); pe = *(const float2*)(ewb + off); \
    pa = *(const float2*)(aab + off); pb = *(const float2*)(bbb + off); \
    pk = *(const float2*)(kb  + off); pv = *(const float2*)(vb  + off); }
#define STSTEP(bf) { *(float2*)&sh[bf][0][lo] = pr; *(float2*)&sh[bf][1][lo] = pe; \
    *(float2*)&sh[bf][2][lo] = pa; *(float2*)&sh[bf][3][lo] = pb; \
    *(float2*)&sh[bf][4][lo] = pk; *(float2*)&sh[bf][5][lo] = pv; }

    LDSTEP(0);
    STSTEP(0);
    __syncwarp();

    for (int t = 0; t < T; t++) {
        const int cur = t & 1;
        if (t + 1 < T) LDSTEP(t + 1);

        float Rv[16], Ev[16], Av[16], Bv[16], Kv[16];
#pragma unroll
        for (int q = 0; q < 4; q++) {
            *(float4*)&Rv[q * 4] = *(const float4*)&sh[cur][0][jb + q * 4];
            *(float4*)&Ev[q * 4] = *(const float4*)&sh[cur][1][jb + q * 4];
            *(float4*)&Av[q * 4] = *(const float4*)&sh[cur][2][jb + q * 4];
            *(float4*)&Bv[q * 4] = *(const float4*)&sh[cur][3][jb + q * 4];
            *(float4*)&Kv[q * 4] = *(const float4*)&sh[cur][4][jb + q * 4];
        }
        const float vt = sh[cur][5][vrow];

        float sa0 = 0.f, sa1 = 0.f, sa2 = 0.f, sa3 = 0.f;
#pragma unroll
        for (int q = 0; q < 4; q++) {
            sa0 = fmaf(S[q * 4 + 0], Av[q * 4 + 0], sa0);
            sa1 = fmaf(S[q * 4 + 1], Av[q * 4 + 1], sa1);
            sa2 = fmaf(S[q * 4 + 2], Av[q * 4 + 2], sa2);
            sa3 = fmaf(S[q * 4 + 3], Av[q * 4 + 3], sa3);
        }
        float sa = (sa0 + sa1) + (sa2 + sa3);
        sa += __shfl_xor_sync(0xffffffffu, sa, 1);
        sa += __shfl_xor_sync(0xffffffffu, sa, 2);

        float o0 = 0.f, o1 = 0.f, o2 = 0.f, o3 = 0.f;
#pragma unroll
        for (int q = 0; q < 4; q++) {
#pragma unroll
            for (int u = 0; u < 4; u++) {
                const int i = q * 4 + u;
                float tmp = fmaf(sa, Bv[i], vt * Kv[i]);
                S[i] = fmaf(S[i], Ev[i], tmp);
                if (u == 0) o0 = fmaf(S[i], Rv[i], o0);
                else if (u == 1) o1 = fmaf(S[i], Rv[i], o1);
                else if (u == 2) o2 = fmaf(S[i], Rv[i], o2);
                else o3 = fmaf(S[i], Rv[i], o3);
            }
        }
        float o = (o0 + o1) + (o2 + o3);
        o += __shfl_xor_sync(0xffffffffu, o, 1);
        o += __shfl_xor_sync(0xffffffffu, o, 2);
        if (jg == 0) y[(size_t)t * C + h * HS + vrow] = o;

        if (t + 1 < T) STSTEP((t + 1) & 1);
        __syncwarp();
    }
#undef LDSTEP
#undef STSTEP
}

// ---------------- K7: GroupNorm + per-head bonus + output gating ----------------
__global__ void k_gn(const float* __restrict__ y, const float* __restrict__ r,
                     const float* __restrict__ kadj, const float* __restrict__ v,
                     const float* __restrict__ gg, const float* __restrict__ rk,
                     const float* __restrict__ lnw, const float* __restrict__ lnb,
                     float* __restrict__ z) {
    const int t = blockIdx.x;
    const int tid = threadIdx.x;
    const int cbase = tid * 4;
    const size_t idx = (size_t)t * C + cbase;
    float4 yv = *(const float4*)(y + idx);
    float s1 = yv.x + yv.y + yv.z + yv.w;
    float s2 = yv.x * yv.x + yv.y * yv.y + yv.z * yv.z + yv.w * yv.w;
    float4 rv = *(const float4*)(r + idx);
    float4 kv = *(const float4*)(kadj + idx);
    float4 rkv = *(const float4*)(rk + cbase);
    float s3 = rv.x * kv.x * rkv.x + rv.y * kv.y * rkv.y +
               rv.z * kv.z * rkv.z + rv.w * kv.w * rkv.w;
#pragma unroll
    for (int off = 8; off > 0; off >>= 1) {
        s1 += __shfl_xor_sync(0xffffffffu, s1, off);
        s2 += __shfl_xor_sync(0xffffffffu, s2, off);
        s3 += __shfl_xor_sync(0xffffffffu, s3, off);
    }
    const float mu = s1 * (1.f / HS);
    const float var = s2 * (1.f / HS) - mu * mu;
    const float inv = rsqrtf(var + EPS_GN);
    float4 vv = *(const float4*)(v + idx);
    float4 gv = *(const float4*)(gg + idx);
    float4 lw = *(const float4*)(lnw + cbase);
    float4 lb = *(const float4*)(lnb + cbase);
    float4 res;
    res.x = (fmaf((yv.x - mu) * inv, lw.x, lb.x) + s3 * vv.x) * gv.x;
    res.y = (fmaf((yv.y - mu) * inv, lw.y, lb.y) + s3 * vv.y) * gv.y;
    res.z = (fmaf((yv.z - mu) * inv, lw.z, lb.z) + s3 * vv.z) * gv.z;
    res.w = (fmaf((yv.w - mu) * inv, lw.w, lb.w) + s3 * vv.w) * gv.w;
    *(float4*)(z + idx) = res;
}

// ---------------- launch ----------------
extern "C" void kernel_launch(void* const* d_in, const int* in_sizes, int n_in,
                              void* d_out, int out_size) {
    const float* x       = (const float*)d_in[0];
    const float* v_first = (const float*)d_in[1];
    const float* x_prev  = (const float*)d_in[2];
    const float* S0      = (const float*)d_in[3];
    const float* m_r = (const float*)d_in[4];
    const float* m_w = (const float*)d_in[5];
    const float* m_k = (const float*)d_in[6];
    const float* m_v = (const float*)d_in[7];
    const float* m_a = (const float*)d_in[8];
    const float* m_g = (const float*)d_in[9];

    // Input-order detection: setup_inputs() dict order interleaves the (C,)
    // vectors w0,a0,v0,k_k,k_a BEFORE the LoRA matrices. Signature order is
    // w0,w1,w2,a0,... . Disambiguate via element counts.
    const float *w0, *w1, *w2, *a0, *a1, *a2, *v0, *v1, *v2, *g1, *g2, *k_k, *k_a, *r_k;
    if (in_sizes[11] == C) {
        // dict order: 10:w0 11:a0 12:v0 13:k_k 14:k_a 15:w1 16:w2 17:a1 18:a2
        //             19:v1 20:v2 21:g1 22:g2 23:r_k
        w0 = (const float*)d_in[10]; a0 = (const float*)d_in[11];
        v0 = (const float*)d_in[12]; k_k = (const float*)d_in[13];
        k_a = (const float*)d_in[14];
        w1 = (const float*)d_in[15]; w2 = (const float*)d_in[16];
        a1 = (const float*)d_in[17]; a2 = (const float*)d_in[18];
        v1 = (const float*)d_in[19]; v2 = (const float*)d_in[20];
        g1 = (const float*)d_in[21]; g2 = (const float*)d_in[22];
        r_k = (const float*)d_in[23];
    } else {
        // signature order
        w0 = (const float*)d_in[10]; w1 = (const float*)d_in[11];
        w2 = (const float*)d_in[12];
        a0 = (const float*)d_in[13]; a1 = (const float*)d_in[14];
        a2 = (const float*)d_in[15];
        v0 = (const float*)d_in[16]; v1 = (const float*)d_in[17];
        v2 = (const float*)d_in[18];
        g1 = (const float*)d_in[19]; g2 = (const float*)d_in[20];
        k_k = (const float*)d_in[21]; k_a = (const float*)d_in[22];
        r_k = (const float*)d_in[23];
    }

    const float* Wr = (const float*)d_in[24];
    const float* Wk = (const float*)d_in[25];
    const float* Wv = (const float*)d_in[26];
    const float* Wo = (const float*)d_in[27];
    const float* lnw = (const float*)d_in[28];
    const float* lnb = (const float*)d_in[29];
    const int*   cu  = (const int*)d_in[30];
    const int ncu = in_sizes[30];
    float* out = (float*)d_out;

    float* s = nullptr;
    cudaGetSymbolAddress((void**)&s, g_scratch);
    const size_t P = (size_t)T * C;
    float* xr = s;          float* xw = s + P;      float* xk = s + 2 * P;
    float* xv = s + 3 * P;  float* xa = s + 4 * P;  float* xg = s + 5 * P;
    float* rb = s + 6 * P;  float* kb = s + 7 * P;  float* vbuf = s + 8 * P;
    float* ewb = s + 9 * P; float* ab = s + 10 * P; float* gbuf = s + 11 * P;
    float* aab = s + 12 * P; float* bbb = s + 13 * P; float* kadj = s + 14 * P;
    float* yb = s + 15 * P;  float* zb = s + 16 * P;
    float* hw = s + 17 * P;
    float* ha = hw + (size_t)T * 64;
    float* hv = ha + (size_t)T * 64;
    float* hg = hv + (size_t)T * 32;

    k_shift_mix<<<T, 256>>>(x, x_prev, cu, ncu, m_r, m_w, m_k, m_v, m_a, m_g,
                            xr, xw, xk, xv, xa, xg);

    dim3 gemm_grid(C / 128, T / 128);
    k_gemm_nt<<<gemm_grid, 256>>>(xr, Wr, rb);
    k_gemm_nt<<<gemm_grid, 256>>>(xk, Wk, kb);
    k_gemm_nt<<<gemm_grid, 256>>>(xv, Wv, vbuf);

    k_stage1<64, 1><<<T / 32, 256>>>(xw, w1, hw);   // tanh
    k_stage1<64, 0><<<T / 32, 256>>>(xa, a1, ha);   // linear
    k_stage1<32, 0><<<T / 32, 256>>>(xv, v1, hv);   // linear
    k_stage1<128, 2><<<T / 32, 256>>>(xg, g1, hg);  // sigmoid

    dim3 s2grid(C / 128, T / 16);
    k_stage2<64, 0><<<s2grid, 128>>>(hw, w2, w0, nullptr, nullptr, ewb);   // ew = exp(w)
    k_stage2<64, 1><<<s2grid, 128>>>(ha, a2, a0, nullptr, nullptr, ab);    // a
    k_stage2<32, 2><<<s2grid, 128>>>(hv, v2, v0, vbuf, v_first, vbuf);     // v mix (in-place)
    k_stage2<128, 3><<<s2grid, 128>>>(hg, g2, nullptr, nullptr, nullptr, gbuf); // g

    k_prep<<<T, 256>>>(kb, ab, k_k, k_a, aab, bbb, kadj);

    k_scan<<<dim3(NH, 8), 32>>>(rb, ewb, aab, bbb, kadj, vbuf, S0, yb);

    k_gn<<<T, 256>>>(yb, rb, kadj, vbuf, gbuf, r_k, lnw, lnb, zb);

    k_gemm_nt<<<gemm_grid, 256>>>(zb, Wo, out);
}